// round 13
// baseline (speedup 1.0000x reference)
#include <cuda_runtime.h>

static constexpr int B = 8;
static constexpr int T = 2048;
static constexpr int C = 1024;
static constexpr int DPB = 64;              // features per block
static constexpr int NCHUNK = C / DPB;      // 16 slabs
static constexpr int GRID = B * NCHUNK;     // 128 blocks -> one wave, ~1/SM
static constexpr int NTHR = 1024;

// Fully fused, barrier-free: each block computes v1[b, d0:d0+64) itself and
// broadcasts exactly those features across all T rows. No inter-block deps.
// 1024 threads: 32 warps for the store phase (occ 50%), 2 features/warp gemv.
__global__ __launch_bounds__(NTHR, 1)
void fused_slab_kernel(const float* __restrict__ x,
                       const float* __restrict__ W,
                       const float* __restrict__ bias,
                       float4* __restrict__ out) {
    __shared__ float4 xs[C / 4];     // 4 KB: x[b, 1, :]
    __shared__ float  slab[DPB];     // v1[b, d0:d0+DPB)

    const int tid  = threadIdx.x;
    const int warp = tid >> 5;
    const int lane = tid & 31;
    const int b    = blockIdx.x >> 4;          // 0..7
    const int d0   = (blockIdx.x & 15) * DPB;  // 0..960

    // ---- Stage x[b,1,:] (starts at offset b*T*C + C) ----
    if (tid < C / 4)
        xs[tid] = reinterpret_cast<const float4*>(x + (size_t)b * T * C + C)[tid];
    __syncthreads();

    // ---- GEMV: warp w computes features d0 + w*2 + {0,1} ----
    const int dbase = d0 + warp * 2;
    float acc0 = 0.0f, acc1 = 0.0f;
    {
        const float4* w0 = reinterpret_cast<const float4*>(W + (size_t)dbase * C);
        const float4* w1 = reinterpret_cast<const float4*>(W + (size_t)(dbase + 1) * C);
#pragma unroll
        for (int i = 0; i < 8; i++) {
            const float4 xv = xs[lane + 32 * i];
            const float4 a  = w0[lane + 32 * i];
            const float4 c  = w1[lane + 32 * i];
            acc0 += a.x * xv.x + a.y * xv.y + a.z * xv.z + a.w * xv.w;
            acc1 += c.x * xv.x + c.y * xv.y + c.z * xv.z + c.w * xv.w;
        }
    }
#pragma unroll
    for (int off = 16; off > 0; off >>= 1) {
        acc0 += __shfl_down_sync(0xffffffffu, acc0, off);
        acc1 += __shfl_down_sync(0xffffffffu, acc1, off);
    }
    if (lane == 0) {
        slab[warp * 2 + 0] = acc0 + bias[dbase + 0];
        slab[warp * 2 + 1] = acc1 + bias[dbase + 1];
    }
    __syncthreads();

    // ---- Broadcast: 64-float slab -> out[b, t, d0:d0+64) for all t ----
    // Thread covers float4 column (tid&15), rows (tid>>4) + 64k.
    // 32 fully independent STG.128 per thread; coalesced 256B segments/warp.
    const int f4 = tid & 15;
    const int r0 = tid >> 4;                  // 0..63
    const float4 val = reinterpret_cast<const float4*>(slab)[f4];

    float4* p = out + ((size_t)b * T + r0) * (C / 4) + (d0 >> 2) + f4;
    const size_t stride = (size_t)64 * (C / 4);   // 64 rows per iteration
#pragma unroll 32
    for (int k = 0; k < T / 64; k++) {
        p[k * stride] = val;
    }
}

extern "C" void kernel_launch(void* const* d_in, const int* in_sizes, int n_in,
                              void* d_out, int out_size) {
    const float* x    = (const float*)d_in[0];
    const float* W    = (const float*)d_in[1];
    const float* bias = (const float*)d_in[2];
    float4* out = reinterpret_cast<float4*>(d_out);

    fused_slab_kernel<<<GRID, NTHR>>>(x, W, bias, out);
}